// round 3
// baseline (speedup 1.0000x reference)
#include <cuda_runtime.h>
#include <math.h>

// Problem constants
#define BB 4
#define TT 4096
#define CC 1024
#define HH 64
#define BQ 64     // query tile rows per block
#define BKT 64    // key tile rows per iteration

// Scratch for projections (no cudaMalloc allowed)
__device__ float g_q[BB * TT * HH];
__device__ float g_k[BB * TT * HH];
__device__ float g_v[BB * TT * HH];

// ---------------------------------------------------------------------------
// Projection GEMM: out[16384,64] = x[16384,1024] @ W[1024,64]
// grid = (16384/128, 3), block = 256. Each thread: 8x4 micro-tile.
// ---------------------------------------------------------------------------
__global__ __launch_bounds__(256) void proj_kernel(
    const float* __restrict__ x,
    const float* __restrict__ Wk,
    const float* __restrict__ Wq,
    const float* __restrict__ Wv)
{
    __shared__ float As[128][33];   // padded to kill column-read conflicts
    __shared__ float Bs[32][64];

    const float* W;
    float* out;
    if (blockIdx.y == 0)      { W = Wq; out = g_q; }
    else if (blockIdx.y == 1) { W = Wk; out = g_k; }
    else                      { W = Wv; out = g_v; }

    const int rowBase = blockIdx.x * 128;
    const int tid = threadIdx.x;
    const int ty = tid >> 4;     // 0..15 -> rows ty*8 .. ty*8+7
    const int tx = tid & 15;     // 0..15 -> cols tx*4 .. tx*4+3

    float acc[8][4];
#pragma unroll
    for (int i = 0; i < 8; i++)
#pragma unroll
        for (int j = 0; j < 4; j++) acc[i][j] = 0.0f;

    const int lr  = tid >> 3;        // 0..31  (A loader row)
    const int lf4 = (tid & 7) * 4;   // 0,4,..28 (A loader col)
    const int lkk = tid >> 4;        // 0..15  (B loader row)
    const int lh4 = (tid & 15) * 4;  // 0..60  (B loader col)

    for (int k0 = 0; k0 < CC; k0 += 32) {
        // Load A tile 128x32 (coalesced float4 per row-chunk)
#pragma unroll
        for (int it = 0; it < 4; it++) {
            int row = lr + it * 32;
            float4 v = *(const float4*)(x + (size_t)(rowBase + row) * CC + k0 + lf4);
            As[row][lf4 + 0] = v.x;
            As[row][lf4 + 1] = v.y;
            As[row][lf4 + 2] = v.z;
            As[row][lf4 + 3] = v.w;
        }
        // Load B tile 32x64
#pragma unroll
        for (int it = 0; it < 2; it++) {
            *(float4*)(&Bs[lkk + it * 16][lh4]) =
                *(const float4*)(W + (size_t)(k0 + lkk + it * 16) * HH + lh4);
        }
        __syncthreads();

#pragma unroll 8
        for (int kk = 0; kk < 32; kk++) {
            float4 b = *(const float4*)(&Bs[kk][tx * 4]);
            float a[8];
#pragma unroll
            for (int i = 0; i < 8; i++) a[i] = As[ty * 8 + i][kk];
#pragma unroll
            for (int i = 0; i < 8; i++) {
                acc[i][0] = fmaf(a[i], b.x, acc[i][0]);
                acc[i][1] = fmaf(a[i], b.y, acc[i][1]);
                acc[i][2] = fmaf(a[i], b.z, acc[i][2]);
                acc[i][3] = fmaf(a[i], b.w, acc[i][3]);
            }
        }
        __syncthreads();
    }

#pragma unroll
    for (int i = 0; i < 8; i++) {
        *(float4*)(out + (size_t)(rowBase + ty * 8 + i) * HH + tx * 4) =
            make_float4(acc[i][0], acc[i][1], acc[i][2], acc[i][3]);
    }
}

// ---------------------------------------------------------------------------
// Flash attention (causal, fp32). grid = B * (T/BQ) blocks, 256 threads.
// Each thread owns a 4x4 micro-tile of S/P and of O.
// Smem = exactly 48KB: Qs + Ks (aliased by Ps) + Vs, 64x64 fp32 each.
// K/Q tiles use additive swizzle (h + 4*row)&63 for conflict-light col reads.
// ---------------------------------------------------------------------------
__global__ __launch_bounds__(256) void attn_kernel(float* __restrict__ out)
{
    __shared__ float Qs[BQ * HH];
    __shared__ float Ks[BKT * HH];
    __shared__ float Vs[BKT * HH];
    float* Ps = Ks;  // P overwrites K after S-phase (sync-guarded)

    const int nT = TT / BQ;                       // 64
    const int b  = blockIdx.x % BB;
    const int qt = nT - 1 - (blockIdx.x / BB);    // biggest tiles first
    const int qbase = qt * BQ;

    const float* qg = g_q + ((size_t)b * TT + qbase) * HH;
    const float* kg = g_k + (size_t)b * TT * HH;
    const float* vg = g_v + (size_t)b * TT * HH;

    const int tid = threadIdx.x;
    const int ty = tid >> 4;   // rows ty*4 .. ty*4+3
    const int tx = tid & 15;   // cols tx*4 .. tx*4+3

    // Load Q tile (swizzled)
#pragma unroll
    for (int it = 0; it < 4; it++) {
        int idx = tid + it * 256;
        int row = idx >> 4;
        int h4  = (idx & 15) * 4;
        float4 v = *(const float4*)(qg + row * HH + h4);
        *(float4*)(&Qs[row * HH + ((h4 + 4 * row) & 63)]) = v;
    }

    float m_i[4], l_i[4], o[4][4];
#pragma unroll
    for (int i = 0; i < 4; i++) {
        m_i[i] = -3.0e38f;
        l_i[i] = 0.0f;
#pragma unroll
        for (int c = 0; c < 4; c++) o[i][c] = 0.0f;
    }

    const float scale = 0.03125f;  // 1024^-0.5

    for (int kt = 0; kt <= qt; kt++) {
        const int kbase = kt * BKT;

        __syncthreads();  // previous O-phase reads of Ps/Vs complete
        // Load K (swizzled) and V (plain) tiles
#pragma unroll
        for (int it = 0; it < 4; it++) {
            int idx = tid + it * 256;
            int row = idx >> 4;
            int h4  = (idx & 15) * 4;
            float4 kv = *(const float4*)(kg + (size_t)(kbase + row) * HH + h4);
            *(float4*)(&Ks[row * HH + ((h4 + 4 * row) & 63)]) = kv;
            float4 vv = *(const float4*)(vg + (size_t)(kbase + row) * HH + h4);
            *(float4*)(&Vs[row * HH + h4]) = vv;
        }
        __syncthreads();

        // ---- S = Q K^T (4x4 per thread) ----
        float s[4][4];
#pragma unroll
        for (int i = 0; i < 4; i++)
#pragma unroll
            for (int j = 0; j < 4; j++) s[i][j] = 0.0f;

#pragma unroll 4
        for (int h = 0; h < HH; h += 4) {
            float4 qv[4], kv[4];
#pragma unroll
            for (int i = 0; i < 4; i++) {
                int r = ty * 4 + i;
                qv[i] = *(const float4*)(&Qs[r * HH + ((h + 4 * r) & 63)]);
            }
#pragma unroll
            for (int j = 0; j < 4; j++) {
                int c = tx * 4 + j;
                kv[j] = *(const float4*)(&Ks[c * HH + ((h + 4 * c) & 63)]);
            }
#pragma unroll
            for (int i = 0; i < 4; i++)
#pragma unroll
                for (int j = 0; j < 4; j++) {
                    s[i][j] = fmaf(qv[i].x, kv[j].x, s[i][j]);
                    s[i][j] = fmaf(qv[i].y, kv[j].y, s[i][j]);
                    s[i][j] = fmaf(qv[i].z, kv[j].z, s[i][j]);
                    s[i][j] = fmaf(qv[i].w, kv[j].w, s[i][j]);
                }
        }

        // ---- mask + online softmax (row stats replicated across 16-lane group) ----
        const bool diag = (kt == qt);
        float p[4][4];
#pragma unroll
        for (int i = 0; i < 4; i++) {
            const int row = qbase + ty * 4 + i;
            float mx = -3.0e38f;
#pragma unroll
            for (int j = 0; j < 4; j++) {
                float sv = s[i][j] * scale;
                if (diag && (kbase + tx * 4 + j) > row) sv = -3.0e38f;
                s[i][j] = sv;
                mx = fmaxf(mx, sv);
            }
#pragma unroll
            for (int off = 8; off; off >>= 1)
                mx = fmaxf(mx, __shfl_xor_sync(0xffffffffu, mx, off));
            const float mnew = fmaxf(m_i[i], mx);
            const float corr = __expf(m_i[i] - mnew);
            float rsum = 0.0f;
#pragma unroll
            for (int j = 0; j < 4; j++) {
                float pv = __expf(s[i][j] - mnew);
                p[i][j] = pv;
                rsum += pv;
            }
#pragma unroll
            for (int off = 8; off; off >>= 1)
                rsum += __shfl_xor_sync(0xffffffffu, rsum, off);
            l_i[i] = l_i[i] * corr + rsum;
            m_i[i] = mnew;
#pragma unroll
            for (int c = 0; c < 4; c++) o[i][c] *= corr;
        }

        __syncthreads();  // all Ks reads done before P overwrites it
#pragma unroll
        for (int i = 0; i < 4; i++) {
            *(float4*)(&Ps[(ty * 4 + i) * BKT + tx * 4]) =
                make_float4(p[i][0], p[i][1], p[i][2], p[i][3]);
        }
        __syncthreads();

        // ---- O += P V ----
#pragma unroll 8
        for (int j = 0; j < BKT; j++) {
            float4 vv = *(const float4*)(&Vs[j * HH + tx * 4]);
            float p0 = Ps[(ty * 4 + 0) * BKT + j];
            float p1 = Ps[(ty * 4 + 1) * BKT + j];
            float p2 = Ps[(ty * 4 + 2) * BKT + j];
            float p3 = Ps[(ty * 4 + 3) * BKT + j];
            o[0][0] = fmaf(p0, vv.x, o[0][0]);
            o[0][1] = fmaf(p0, vv.y, o[0][1]);
            o[0][2] = fmaf(p0, vv.z, o[0][2]);
            o[0][3] = fmaf(p0, vv.w, o[0][3]);
            o[1][0] = fmaf(p1, vv.x, o[1][0]);
            o[1][1] = fmaf(p1, vv.y, o[1][1]);
            o[1][2] = fmaf(p1, vv.z, o[1][2]);
            o[1][3] = fmaf(p1, vv.w, o[1][3]);
            o[2][0] = fmaf(p2, vv.x, o[2][0]);
            o[2][1] = fmaf(p2, vv.y, o[2][1]);
            o[2][2] = fmaf(p2, vv.z, o[2][2]);
            o[2][3] = fmaf(p2, vv.w, o[2][3]);
            o[3][0] = fmaf(p3, vv.x, o[3][0]);
            o[3][1] = fmaf(p3, vv.y, o[3][1]);
            o[3][2] = fmaf(p3, vv.z, o[3][2]);
            o[3][3] = fmaf(p3, vv.w, o[3][3]);
        }
    }

    // Epilogue: normalize and write out [B, T, H]
#pragma unroll
    for (int i = 0; i < 4; i++) {
        float inv = 1.0f / l_i[i];
        *(float4*)(out + ((size_t)b * TT + qbase + ty * 4 + i) * HH + tx * 4) =
            make_float4(o[i][0] * inv, o[i][1] * inv, o[i][2] * inv, o[i][3] * inv);
    }
}

// ---------------------------------------------------------------------------
// Inputs (metadata order): x [4,4096,1024] f32, Wk [1024,64], Wq [1024,64],
// Wv [1024,64]. Output: [4,4096,64] f32.
// ---------------------------------------------------------------------------
extern "C" void kernel_launch(void* const* d_in, const int* in_sizes, int n_in,
                              void* d_out, int out_size)
{
    const float* x  = (const float*)d_in[0];
    const float* Wk = (const float*)d_in[1];
    const float* Wq = (const float*)d_in[2];
    const float* Wv = (const float*)d_in[3];
    float* out = (float*)d_out;

    dim3 gProj((BB * TT) / 128, 3);
    proj_kernel<<<gProj, 256>>>(x, Wk, Wq, Wv);

    attn_kernel<<<BB * (TT / BQ), 256>>>(out);
}

// round 4
// speedup vs baseline: 1.3159x; 1.3159x over previous
#include <cuda_runtime.h>
#include <math.h>

// Problem constants
#define BB 4
#define TT 4096
#define CC 1024
#define HH 64
#define BQ 64     // query tile rows per block
#define BKT 64    // key tile rows per iteration
#define NT (TT / BQ)   // 64 query tiles per batch
#define CHUNK 8        // key-tiles per split block
#define MAXSPL 8       // max splits per (b, qt)

// Scratch (no cudaMalloc allowed)
__device__ float g_q[BB * TT * HH];
__device__ float g_k[BB * TT * HH];
__device__ float g_v[BB * TT * HH];
// split-KV partials: unnormalized O, row max m, row sum l
__device__ float g_opart[BB * NT * MAXSPL * BQ * HH];   // 33.5 MB
__device__ float g_mpart[BB * NT * MAXSPL * BQ];
__device__ float g_lpart[BB * NT * MAXSPL * BQ];

// ---------------------------------------------------------------------------
// Projection GEMM: out[16384,64] = x[16384,1024] @ W[1024,64]
// grid = (16384/128, 3), block = 256. Each thread: 8x4 micro-tile.
// ---------------------------------------------------------------------------
__global__ __launch_bounds__(256) void proj_kernel(
    const float* __restrict__ x,
    const float* __restrict__ Wk,
    const float* __restrict__ Wq,
    const float* __restrict__ Wv)
{
    __shared__ float As[128][33];
    __shared__ float Bs[32][64];

    const float* W;
    float* out;
    if (blockIdx.y == 0)      { W = Wq; out = g_q; }
    else if (blockIdx.y == 1) { W = Wk; out = g_k; }
    else                      { W = Wv; out = g_v; }

    const int rowBase = blockIdx.x * 128;
    const int tid = threadIdx.x;
    const int ty = tid >> 4;
    const int tx = tid & 15;

    float acc[8][4];
#pragma unroll
    for (int i = 0; i < 8; i++)
#pragma unroll
        for (int j = 0; j < 4; j++) acc[i][j] = 0.0f;

    const int lr  = tid >> 3;
    const int lf4 = (tid & 7) * 4;
    const int lkk = tid >> 4;
    const int lh4 = (tid & 15) * 4;

    for (int k0 = 0; k0 < CC; k0 += 32) {
#pragma unroll
        for (int it = 0; it < 4; it++) {
            int row = lr + it * 32;
            float4 v = *(const float4*)(x + (size_t)(rowBase + row) * CC + k0 + lf4);
            As[row][lf4 + 0] = v.x;
            As[row][lf4 + 1] = v.y;
            As[row][lf4 + 2] = v.z;
            As[row][lf4 + 3] = v.w;
        }
#pragma unroll
        for (int it = 0; it < 2; it++) {
            *(float4*)(&Bs[lkk + it * 16][lh4]) =
                *(const float4*)(W + (size_t)(k0 + lkk + it * 16) * HH + lh4);
        }
        __syncthreads();

#pragma unroll 8
        for (int kk = 0; kk < 32; kk++) {
            float4 b = *(const float4*)(&Bs[kk][tx * 4]);
            float a[8];
#pragma unroll
            for (int i = 0; i < 8; i++) a[i] = As[ty * 8 + i][kk];
#pragma unroll
            for (int i = 0; i < 8; i++) {
                acc[i][0] = fmaf(a[i], b.x, acc[i][0]);
                acc[i][1] = fmaf(a[i], b.y, acc[i][1]);
                acc[i][2] = fmaf(a[i], b.z, acc[i][2]);
                acc[i][3] = fmaf(a[i], b.w, acc[i][3]);
            }
        }
        __syncthreads();
    }

#pragma unroll
    for (int i = 0; i < 8; i++) {
        *(float4*)(out + (size_t)(rowBase + ty * 8 + i) * HH + tx * 4) =
            make_float4(acc[i][0], acc[i][1], acc[i][2], acc[i][3]);
    }
}

// ---------------------------------------------------------------------------
// Split-KV flash attention (causal, fp32).
// grid = (NT, MAXSPL, BB); block = 256. Each active block handles <= CHUNK
// key-tiles of one (b, qt) query tile and emits an unnormalized partial.
// Smem = 48 KB (Qs + Ks(aliased by Ps) + Vs). launch_bounds minBlocks=3.
// ---------------------------------------------------------------------------
__global__ __launch_bounds__(256, 3) void attn_kernel()
{
    __shared__ float Qs[BQ * HH];
    __shared__ float Ks[BKT * HH];
    __shared__ float Vs[BKT * HH];
    float* Ps = Ks;  // P overwrites K after S-phase (sync-guarded)

    const int qt    = blockIdx.x;
    const int split = blockIdx.y;
    const int b     = blockIdx.z;
    const int nspl  = (qt + CHUNK) / CHUNK;      // ceil((qt+1)/CHUNK)
    if (split >= nspl) return;

    const int ktBeg = split * CHUNK;
    const int ktEnd = min(ktBeg + CHUNK, qt + 1);
    const int qbase = qt * BQ;

    const float* qg = g_q + ((size_t)b * TT + qbase) * HH;
    const float* kg = g_k + (size_t)b * TT * HH;
    const float* vg = g_v + (size_t)b * TT * HH;

    const int tid = threadIdx.x;
    const int ty = tid >> 4;   // rows ty*4 .. ty*4+3
    const int tx = tid & 15;   // cols tx*4 .. tx*4+3

    // Load Q tile (swizzled)
#pragma unroll
    for (int it = 0; it < 4; it++) {
        int idx = tid + it * 256;
        int row = idx >> 4;
        int h4  = (idx & 15) * 4;
        float4 v = *(const float4*)(qg + row * HH + h4);
        *(float4*)(&Qs[row * HH + ((h4 + 4 * row) & 63)]) = v;
    }

    float m_i[4], l_i[4], o[4][4];
#pragma unroll
    for (int i = 0; i < 4; i++) {
        m_i[i] = -3.0e38f;
        l_i[i] = 0.0f;
#pragma unroll
        for (int c = 0; c < 4; c++) o[i][c] = 0.0f;
    }

    const float scale = 0.03125f;  // 1024^-0.5

    for (int kt = ktBeg; kt < ktEnd; kt++) {
        const int kbase = kt * BKT;

        __syncthreads();  // previous O-phase reads of Ps/Vs complete
#pragma unroll
        for (int it = 0; it < 4; it++) {
            int idx = tid + it * 256;
            int row = idx >> 4;
            int h4  = (idx & 15) * 4;
            float4 kv = *(const float4*)(kg + (size_t)(kbase + row) * HH + h4);
            *(float4*)(&Ks[row * HH + ((h4 + 4 * row) & 63)]) = kv;
            float4 vv = *(const float4*)(vg + (size_t)(kbase + row) * HH + h4);
            *(float4*)(&Vs[row * HH + h4]) = vv;
        }
        __syncthreads();

        // ---- S = Q K^T (4x4 per thread) ----
        float s[4][4];
#pragma unroll
        for (int i = 0; i < 4; i++)
#pragma unroll
            for (int j = 0; j < 4; j++) s[i][j] = 0.0f;

#pragma unroll 4
        for (int h = 0; h < HH; h += 4) {
            float4 qv[4], kv[4];
#pragma unroll
            for (int i = 0; i < 4; i++) {
                int r = ty * 4 + i;
                qv[i] = *(const float4*)(&Qs[r * HH + ((h + 4 * r) & 63)]);
            }
#pragma unroll
            for (int j = 0; j < 4; j++) {
                int c = tx * 4 + j;
                kv[j] = *(const float4*)(&Ks[c * HH + ((h + 4 * c) & 63)]);
            }
#pragma unroll
            for (int i = 0; i < 4; i++)
#pragma unroll
                for (int j = 0; j < 4; j++) {
                    s[i][j] = fmaf(qv[i].x, kv[j].x, s[i][j]);
                    s[i][j] = fmaf(qv[i].y, kv[j].y, s[i][j]);
                    s[i][j] = fmaf(qv[i].z, kv[j].z, s[i][j]);
                    s[i][j] = fmaf(qv[i].w, kv[j].w, s[i][j]);
                }
        }

        // ---- mask + online softmax (row stats across 16-lane tx group) ----
        const bool diag = (kt == qt);
        float p[4][4];
#pragma unroll
        for (int i = 0; i < 4; i++) {
            const int row = qbase + ty * 4 + i;
            float mx = -3.0e38f;
#pragma unroll
            for (int j = 0; j < 4; j++) {
                float sv = s[i][j] * scale;
                if (diag && (kbase + tx * 4 + j) > row) sv = -3.0e38f;
                s[i][j] = sv;
                mx = fmaxf(mx, sv);
            }
#pragma unroll
            for (int off = 8; off; off >>= 1)
                mx = fmaxf(mx, __shfl_xor_sync(0xffffffffu, mx, off));
            const float mnew = fmaxf(m_i[i], mx);
            const float corr = __expf(m_i[i] - mnew);
            float rsum = 0.0f;
#pragma unroll
            for (int j = 0; j < 4; j++) {
                float pv = __expf(s[i][j] - mnew);
                p[i][j] = pv;
                rsum += pv;
            }
#pragma unroll
            for (int off = 8; off; off >>= 1)
                rsum += __shfl_xor_sync(0xffffffffu, rsum, off);
            l_i[i] = l_i[i] * corr + rsum;
            m_i[i] = mnew;
#pragma unroll
            for (int c = 0; c < 4; c++) o[i][c] *= corr;
        }

        __syncthreads();  // all Ks reads done before P overwrites it
#pragma unroll
        for (int i = 0; i < 4; i++) {
            *(float4*)(&Ps[(ty * 4 + i) * BKT + tx * 4]) =
                make_float4(p[i][0], p[i][1], p[i][2], p[i][3]);
        }
        __syncthreads();

        // ---- O += P V : all loads vectorized (8x LDS.128 per 64 FMA) ----
#pragma unroll 4
        for (int j4 = 0; j4 < BKT / 4; j4++) {
            float4 v0 = *(const float4*)(&Vs[(4 * j4 + 0) * HH + tx * 4]);
            float4 v1 = *(const float4*)(&Vs[(4 * j4 + 1) * HH + tx * 4]);
            float4 v2 = *(const float4*)(&Vs[(4 * j4 + 2) * HH + tx * 4]);
            float4 v3 = *(const float4*)(&Vs[(4 * j4 + 3) * HH + tx * 4]);
#pragma unroll
            for (int i = 0; i < 4; i++) {
                float4 pv = *(const float4*)(&Ps[(ty * 4 + i) * BKT + 4 * j4]);
                o[i][0] = fmaf(pv.x, v0.x, o[i][0]);
                o[i][1] = fmaf(pv.x, v0.y, o[i][1]);
                o[i][2] = fmaf(pv.x, v0.z, o[i][2]);
                o[i][3] = fmaf(pv.x, v0.w, o[i][3]);
                o[i][0] = fmaf(pv.y, v1.x, o[i][0]);
                o[i][1] = fmaf(pv.y, v1.y, o[i][1]);
                o[i][2] = fmaf(pv.y, v1.z, o[i][2]);
                o[i][3] = fmaf(pv.y, v1.w, o[i][3]);
                o[i][0] = fmaf(pv.z, v2.x, o[i][0]);
                o[i][1] = fmaf(pv.z, v2.y, o[i][1]);
                o[i][2] = fmaf(pv.z, v2.z, o[i][2]);
                o[i][3] = fmaf(pv.z, v2.w, o[i][3]);
                o[i][0] = fmaf(pv.w, v3.x, o[i][0]);
                o[i][1] = fmaf(pv.w, v3.y, o[i][1]);
                o[i][2] = fmaf(pv.w, v3.z, o[i][2]);
                o[i][3] = fmaf(pv.w, v3.w, o[i][3]);
            }
        }
    }

    // Epilogue: write unnormalized partial + row stats
    const size_t pidx = (size_t)((b * NT + qt) * MAXSPL + split);
    float* op = g_opart + pidx * (BQ * HH);
#pragma unroll
    for (int i = 0; i < 4; i++) {
        *(float4*)(op + (ty * 4 + i) * HH + tx * 4) =
            make_float4(o[i][0], o[i][1], o[i][2], o[i][3]);
        if (tx == 0) {
            g_mpart[pidx * BQ + ty * 4 + i] = m_i[i];
            g_lpart[pidx * BQ + ty * 4 + i] = l_i[i];
        }
    }
}

// ---------------------------------------------------------------------------
// Merge: combine <= MAXSPL partials per row. One thread per (row, 4 cols).
// grid = 1024 blocks x 256 threads = 16384 rows x 16 col-groups.
// ---------------------------------------------------------------------------
__global__ __launch_bounds__(256) void merge_kernel(float* __restrict__ out)
{
    const int gid = blockIdx.x * 256 + threadIdx.x;
    const int row = gid >> 4;          // 0 .. B*T-1
    const int cx  = (gid & 15) * 4;
    const int b  = row >> 12;          // row / TT
    const int t  = row & (TT - 1);
    const int qt = t >> 6;             // t / BQ
    const int r  = t & (BQ - 1);
    const int ns = (qt + CHUNK) / CHUNK;

    const size_t mlBase = (size_t)(b * NT + qt) * MAXSPL * BQ + r;

    float M = -3.0e38f;
    for (int s = 0; s < ns; s++)
        M = fmaxf(M, g_mpart[mlBase + (size_t)s * BQ]);

    float L = 0.0f;
    float a0 = 0.0f, a1 = 0.0f, a2 = 0.0f, a3 = 0.0f;
    for (int s = 0; s < ns; s++) {
        const float w = __expf(g_mpart[mlBase + (size_t)s * BQ] - M);
        L += w * g_lpart[mlBase + (size_t)s * BQ];
        const float* op = g_opart
            + (size_t)((b * NT + qt) * MAXSPL + s) * (BQ * HH) + r * HH + cx;
        float4 v = *(const float4*)op;
        a0 = fmaf(w, v.x, a0);
        a1 = fmaf(w, v.y, a1);
        a2 = fmaf(w, v.z, a2);
        a3 = fmaf(w, v.w, a3);
    }
    const float inv = 1.0f / L;
    *(float4*)(out + (size_t)row * HH + cx) =
        make_float4(a0 * inv, a1 * inv, a2 * inv, a3 * inv);
}

// ---------------------------------------------------------------------------
// Inputs: x [4,4096,1024] f32, Wk, Wq, Wv [1024,64] f32. Out: [4,4096,64] f32.
// ---------------------------------------------------------------------------
extern "C" void kernel_launch(void* const* d_in, const int* in_sizes, int n_in,
                              void* d_out, int out_size)
{
    const float* x  = (const float*)d_in[0];
    const float* Wk = (const float*)d_in[1];
    const float* Wq = (const float*)d_in[2];
    const float* Wv = (const float*)d_in[3];
    float* out = (float*)d_out;

    dim3 gProj((BB * TT) / 128, 3);
    proj_kernel<<<gProj, 256>>>(x, Wk, Wq, Wv);

    dim3 gAttn(NT, MAXSPL, BB);
    attn_kernel<<<gAttn, 256>>>();

    merge_kernel<<<(BB * TT * 16) / 256, 256>>>(out);
}